// round 8
// baseline (speedup 1.0000x reference)
#include <cuda_runtime.h>
#include <cuda_bf16.h>
#include <math.h>
#include <stdint.h>

#define NN   100000
#define EE   1600000
#define FIN  700
#define K0P  704
#define HH   128
#define EPSV 1e-5f

// ---------------- scratch (static device globals; zero-init, no runtime alloc) ----
__device__ float g_h  [(size_t)NN * HH];
__device__ float g_hc [(size_t)NN * 256];        // [self(128) | neigh(128)] per row
__device__ float g_z  [(size_t)NN * 64];
__device__ float g_denom[NN];
__device__ int   g_deg[NN];
__device__ int   g_rowptr[NN + 1];
__device__ int   g_colidx[EE];
__device__ int   g_bsums[128];
__device__ __align__(16) float g_stats[256];
__device__ __align__(16) float g_ab[256];

// bf16 split weights (A operands are split in-GEMM)
__device__ __nv_bfloat16 g_B0h[256 * K0P];
__device__ __nv_bfloat16 g_B0l[256 * K0P];
__device__ __nv_bfloat16 g_BLh[3 * 256 * HH];
__device__ __nv_bfloat16 g_BLl[3 * 256 * HH];

// ---------------- helpers ------------------------------------------------------
__device__ __forceinline__ void split_bf16(float x, __nv_bfloat16& h, __nv_bfloat16& l) {
    h = __float2bfloat16(x);
    l = __float2bfloat16(x - __bfloat162float(h));
}
__device__ __forceinline__ uint32_t pkbf2(__nv_bfloat16 a, __nv_bfloat16 b) {
    __nv_bfloat162 t = __halves2bfloat162(a, b);
    return *reinterpret_cast<uint32_t*>(&t);
}
__device__ __forceinline__ void cp16(uint32_t s, const void* g) {
    asm volatile("cp.async.cg.shared.global [%0], [%1], 16;" :: "r"(s), "l"(g));
}
__device__ __forceinline__ void ldsm4(uint32_t& r0, uint32_t& r1, uint32_t& r2, uint32_t& r3, uint32_t a) {
    asm volatile("ldmatrix.sync.aligned.m8n8.x4.shared.b16 {%0,%1,%2,%3}, [%4];"
                 : "=r"(r0), "=r"(r1), "=r"(r2), "=r"(r3) : "r"(a));
}
__device__ __forceinline__ void mma16816(float* c, const uint32_t* a, const uint32_t* b) {
    asm volatile("mma.sync.aligned.m16n8k16.row.col.f32.bf16.bf16.f32 "
                 "{%0,%1,%2,%3}, {%4,%5,%6,%7}, {%8,%9}, {%0,%1,%2,%3};"
                 : "+f"(c[0]), "+f"(c[1]), "+f"(c[2]), "+f"(c[3])
                 : "r"(a[0]), "r"(a[1]), "r"(a[2]), "r"(a[3]), "r"(b[0]), "r"(b[1]));
}

// ---------------- CSR construction --------------------------------------------
__global__ void k_zero_deg() {
    int i = blockIdx.x * blockDim.x + threadIdx.x;
    if (i < NN) g_deg[i] = 0;
}
__global__ void k_count(const int* __restrict__ graph) {
    int e = blockIdx.x * blockDim.x + threadIdx.x;
    if (e < EE) atomicAdd(&g_deg[graph[2 * e + 1]], 1);
}
__global__ void k_scan1() {
    __shared__ int s[1024];
    int tid = threadIdx.x;
    int i = blockIdx.x * 1024 + tid;
    int v = (i < NN) ? g_deg[i] : 0;
    s[tid] = v;
    __syncthreads();
    #pragma unroll
    for (int off = 1; off < 1024; off <<= 1) {
        int t = (tid >= off) ? s[tid - off] : 0;
        __syncthreads();
        s[tid] += t;
        __syncthreads();
    }
    if (i < NN) g_rowptr[i + 1] = s[tid];
    if (tid == 1023) g_bsums[blockIdx.x] = s[1023];
}
__global__ void k_scan2() {
    if (threadIdx.x == 0) {
        const int nb = (NN + 1023) / 1024;
        int acc = 0;
        for (int i = 0; i < nb; i++) { int t = g_bsums[i]; g_bsums[i] = acc; acc += t; }
    }
}
__global__ void k_scan3() {
    int i = blockIdx.x * blockDim.x + threadIdx.x;
    if (i >= NN) return;
    g_rowptr[i + 1] += g_bsums[i >> 10];
    if (i == 0) g_rowptr[0] = 0;
    int d = g_deg[i];
    g_denom[i] = (float)((d > 1) ? d : 1);
    g_deg[i] = 0;
}
__global__ void k_fill(const int* __restrict__ graph) {
    int e = blockIdx.x * blockDim.x + threadIdx.x;
    if (e >= EE) return;
    int src = graph[2 * e + 0];
    int dst = graph[2 * e + 1];
    int pos = g_rowptr[dst] + atomicAdd(&g_deg[dst], 1);
    g_colidx[pos] = src;
}

// ---------------- weight conversion --------------------------------------------
__global__ void k_convW0(const float* __restrict__ Ws, const float* __restrict__ Wn) {
    int idx = blockIdx.x * blockDim.x + threadIdx.x;
    if (idx >= 256 * K0P) return;
    int n = idx / K0P, k = idx % K0P;
    float v = 0.f;
    if (k < FIN) v = (n < HH) ? Ws[(size_t)k * HH + n] : Wn[(size_t)k * HH + (n - HH)];
    split_bf16(v, g_B0h[idx], g_B0l[idx]);
}
__global__ void k_convWL(const float* __restrict__ Ws, const float* __restrict__ Wn) {
    int idx = blockIdx.x * blockDim.x + threadIdx.x;
    if (idx >= 3 * 256 * HH) return;
    int l = idx / (256 * HH);
    int rem = idx % (256 * HH);
    int n = rem / HH, k = rem % HH;
    float v = (n < HH) ? Ws[(size_t)l * HH * HH + k * HH + n]
                       : Wn[(size_t)l * HH * HH + k * HH + (n - HH)];
    split_bf16(v, g_BLh[idx], g_BLl[idx]);
}

// ---------------- split-precision tensor GEMM, fp32 A fed in-kernel ------------
// C cols [bx*128, bx*128+128) = A[M][K](fp32) @ Bcat[bx half]^T (bf16 hi/lo)
// BM=128, BN=128, BK=32, 256 threads (8 warps, warp tile 64x32), 2-stage cp.async.
// Stage: [Ah][Al][Bh][Bl], each 128 rows x 40 halfs (80B stride). 80KB dyn smem.
#define TILE_B 10240
#define STAGE_B 40960
__global__ void __launch_bounds__(256) gemm_split(
    const float* __restrict__ A, int K, int Kpad,
    const __nv_bfloat16* __restrict__ Bh0, const __nv_bfloat16* __restrict__ Bl0,
    float* __restrict__ C, int M, int NCs)
{
    extern __shared__ __align__(16) char smem[];
    const uint32_t sb = (uint32_t)__cvta_generic_to_shared(smem);
    const int tid = threadIdx.x;
    const int bx = blockIdx.x, by = blockIdx.y;
    const int row0 = by * 128;
    const __nv_bfloat16* Bh = Bh0 + (size_t)bx * 128 * Kpad;
    const __nv_bfloat16* Bl = Bl0 + (size_t)bx * 128 * Kpad;
    const int KT = Kpad >> 5;

    const int ar = tid >> 1, aq = tid & 1;   // A granule: row ar, 16-float half aq
    const int agr = row0 + ar;
    const float* Arow = A + (size_t)agr * K;

    float av[16];

    auto ldgA = [&](int kt) {
        #pragma unroll
        for (int i = 0; i < 4; i++) {
            int kb = kt * 32 + aq * 16 + i * 4;
            float4 t = make_float4(0.f, 0.f, 0.f, 0.f);
            if (agr < M && kb + 3 < K) t = *reinterpret_cast<const float4*>(Arow + kb);
            av[i * 4 + 0] = t.x; av[i * 4 + 1] = t.y;
            av[i * 4 + 2] = t.z; av[i * 4 + 3] = t.w;
        }
    };
    auto stsA = [&](int stage) {
        uint32_t hi[8], lo[8];
        #pragma unroll
        for (int j = 0; j < 8; j++) {
            __nv_bfloat16 h0, l0, h1, l1;
            split_bf16(av[j * 2], h0, l0);
            split_bf16(av[j * 2 + 1], h1, l1);
            hi[j] = pkbf2(h0, h1);
            lo[j] = pkbf2(l0, l1);
        }
        char* dst = smem + stage * STAGE_B + ar * 80 + aq * 32;
        *reinterpret_cast<uint4*>(dst)               = make_uint4(hi[0], hi[1], hi[2], hi[3]);
        *reinterpret_cast<uint4*>(dst + 16)          = make_uint4(hi[4], hi[5], hi[6], hi[7]);
        *reinterpret_cast<uint4*>(dst + TILE_B)      = make_uint4(lo[0], lo[1], lo[2], lo[3]);
        *reinterpret_cast<uint4*>(dst + TILE_B + 16) = make_uint4(lo[4], lo[5], lo[6], lo[7]);
    };
    auto cpB = [&](int kt) {
        uint32_t base = sb + (uint32_t)(kt & 1) * STAGE_B + 2u * TILE_B;
        int r = tid >> 1, q = tid & 1;
        uint32_t so = base + (uint32_t)(r * 80 + q * 32);
        size_t gb = (size_t)r * Kpad + kt * 32 + q * 16;
        cp16(so, Bh + gb);
        cp16(so + 16, Bh + gb + 8);
        cp16(so + TILE_B, Bl + gb);
        cp16(so + TILE_B + 16, Bl + gb + 8);
        asm volatile("cp.async.commit_group;");
    };

    // prologue: A(0) split+stored, A(1) held in regs, B(0), B(1) in flight
    ldgA(0);
    stsA(0);
    ldgA(1);
    cpB(0);
    cpB(1);

    const int lane = tid & 31, w = tid >> 5;
    const int wm = w >> 2, wn = w & 3;           // 2 x 4 warp grid, warp tile 64x32
    const int lr = lane >> 2, lc = lane & 3;
    const int mat = lane >> 3, r8 = lane & 7;

    float acc[4][4][4];
    #pragma unroll
    for (int a = 0; a < 4; a++)
        #pragma unroll
        for (int b = 0; b < 4; b++)
            #pragma unroll
            for (int d = 0; d < 4; d++) acc[a][b][d] = 0.f;

    for (int kt = 0; kt < KT; ++kt) {
        if (kt < KT - 1) asm volatile("cp.async.wait_group 1;");
        else             asm volatile("cp.async.wait_group 0;");
        __syncthreads();
        uint32_t base = sb + (uint32_t)(kt & 1) * STAGE_B;

        #pragma unroll
        for (int kk = 0; kk < 2; ++kk) {
            const int k0 = kk * 16;
            uint32_t bh[2][4], bl[2][4];
            #pragma unroll
            for (int p = 0; p < 2; p++) {
                int brow = wn * 32 + p * 16 + r8 + (mat >> 1) * 8;
                uint32_t addr = base + 2u * TILE_B + (uint32_t)(brow * 80 + (k0 + (mat & 1) * 8) * 2);
                ldsm4(bh[p][0], bh[p][1], bh[p][2], bh[p][3], addr);
                ldsm4(bl[p][0], bl[p][1], bl[p][2], bl[p][3], addr + TILE_B);
            }
            #pragma unroll
            for (int mf = 0; mf < 4; ++mf) {
                int arow = wm * 64 + mf * 16 + r8 + (mat & 1) * 8;
                uint32_t aaddr = base + (uint32_t)(arow * 80 + (k0 + (mat >> 1) * 8) * 2);
                uint32_t ahr[4], alr[4];
                ldsm4(ahr[0], ahr[1], ahr[2], ahr[3], aaddr);
                ldsm4(alr[0], alr[1], alr[2], alr[3], aaddr + TILE_B);
                #pragma unroll
                for (int nf = 0; nf < 4; ++nf) {
                    const uint32_t* bhp = &bh[nf >> 1][(nf & 1) * 2];
                    const uint32_t* blp = &bl[nf >> 1][(nf & 1) * 2];
                    mma16816(acc[mf][nf], ahr, bhp);
                    mma16816(acc[mf][nf], alr, bhp);
                    mma16816(acc[mf][nf], ahr, blp);
                }
            }
        }

        // feed stage s^1 with A(kt+1) (consumed after next barrier), start A(kt+2)
        if (kt + 1 < KT) stsA((kt + 1) & 1);
        if (kt + 2 < KT) ldgA(kt + 2);
        __syncthreads();
        if (kt + 2 < KT) cpB(kt + 2);    // refill B of stage kt&1 (reads done)
    }

    #pragma unroll
    for (int mf = 0; mf < 4; ++mf) {
        #pragma unroll
        for (int nf = 0; nf < 4; ++nf) {
            int r = row0 + wm * 64 + mf * 16 + lr;
            int cc = bx * 128 + wn * 32 + nf * 8 + lc * 2;
            if (r < M)
                *reinterpret_cast<float2*>(C + (size_t)r * NCs + cc) =
                    make_float2(acc[mf][nf][0], acc[mf][nf][1]);
            if (r + 8 < M)
                *reinterpret_cast<float2*>(C + (size_t)(r + 8) * NCs + cc) =
                    make_float2(acc[mf][nf][2], acc[mf][nf][3]);
        }
    }
}

// ---------------- fp32 SGEMM (head only) ---------------------------------------
template <int BN, int TN>
__global__ __launch_bounds__(256) void sgemm(const float* __restrict__ A,
                                             const float* __restrict__ B,
                                             float* __restrict__ C,
                                             int M, int K, int NC) {
    constexpr int BM = 128, BK = 8, TM = 8;
    constexpr int TX = BN / TN;
    __shared__ float As[BK][BM];
    __shared__ float Bs[BK][BN];
    const int tid = threadIdx.x;
    const int tx = tid % TX;
    const int ty = tid / TX;
    const int row0 = blockIdx.y * BM;
    const int col0 = blockIdx.x * BN;
    float acc[TM][TN];
    #pragma unroll
    for (int i = 0; i < TM; i++)
        #pragma unroll
        for (int j = 0; j < TN; j++) acc[i][j] = 0.f;
    for (int kk = 0; kk < K; kk += BK) {
        {
            constexpr int NF4 = BM * BK / 4;
            #pragma unroll
            for (int t = tid; t < NF4; t += 256) {
                int r = t / (BK / 4);
                int q = t % (BK / 4);
                float4 v = make_float4(0.f, 0.f, 0.f, 0.f);
                int gr = row0 + r, gk = kk + q * 4;
                if (gr < M && gk < K)
                    v = *reinterpret_cast<const float4*>(A + (size_t)gr * K + gk);
                As[q * 4 + 0][r] = v.x; As[q * 4 + 1][r] = v.y;
                As[q * 4 + 2][r] = v.z; As[q * 4 + 3][r] = v.w;
            }
        }
        {
            constexpr int NF4 = BK * BN / 4;
            #pragma unroll
            for (int t = tid; t < NF4; t += 256) {
                int r = t / (BN / 4);
                int q = t % (BN / 4);
                float4 v = make_float4(0.f, 0.f, 0.f, 0.f);
                int gk = kk + r;
                if (gk < K)
                    v = *reinterpret_cast<const float4*>(B + (size_t)gk * NC + col0 + q * 4);
                *reinterpret_cast<float4*>(&Bs[r][q * 4]) = v;
            }
        }
        __syncthreads();
        #pragma unroll
        for (int k = 0; k < BK; k++) {
            float a[TM], b[TN];
            #pragma unroll
            for (int i = 0; i < TM; i++) a[i] = As[k][ty * TM + i];
            #pragma unroll
            for (int j = 0; j < TN; j++) b[j] = Bs[k][tx * TN + j];
            #pragma unroll
            for (int i = 0; i < TM; i++)
                #pragma unroll
                for (int j = 0; j < TN; j++) acc[i][j] = fmaf(a[i], b[j], acc[i][j]);
        }
        __syncthreads();
    }
    #pragma unroll
    for (int i = 0; i < TM; i++) {
        int gr = row0 + ty * TM + i;
        if (gr >= M) continue;
        #pragma unroll
        for (int j = 0; j < TN; j += 4) {
            float4 v = make_float4(acc[i][j], acc[i][j + 1], acc[i][j + 2], acc[i][j + 3]);
            *reinterpret_cast<float4*>(C + (size_t)gr * NC + col0 + tx * TN + j) = v;
        }
    }
}

// ---------------- fused CSR gather + bias + BN stats (warp-per-node) -----------
#define AGG_NPW 16
__global__ void __launch_bounds__(256) k_aggcomb(float* __restrict__ hc,
                                                 const float* __restrict__ bias) {
    __shared__ float sst[256];
    const int tid = threadIdx.x;
    const int lane = tid & 31;
    const int gw = blockIdx.x * 8 + (tid >> 5);
    const int c4 = lane * 4;
    const int n0 = gw * AGG_NPW;
    if (tid < 256) sst[tid] = 0.f;
    __syncthreads();

    if (n0 < NN) {
        const int n1 = min(n0 + AGG_NPW, NN);
        float4 bb = *reinterpret_cast<const float4*>(bias + c4);
        float s0 = 0.f, s1 = 0.f, s2 = 0.f, s3 = 0.f;
        float q0 = 0.f, q1 = 0.f, q2 = 0.f, q3 = 0.f;

        for (int node = n0; node < n1; node++) {
            int p = g_rowptr[node];
            const int e = g_rowptr[node + 1];
            float4 acc = make_float4(0.f, 0.f, 0.f, 0.f);
            for (; p + 3 < e; p += 4) {
                int i0 = __ldg(&g_colidx[p]);
                int i1 = __ldg(&g_colidx[p + 1]);
                int i2 = __ldg(&g_colidx[p + 2]);
                int i3 = __ldg(&g_colidx[p + 3]);
                float4 v0 = *reinterpret_cast<const float4*>(hc + (size_t)i0 * 256 + HH + c4);
                float4 v1 = *reinterpret_cast<const float4*>(hc + (size_t)i1 * 256 + HH + c4);
                float4 v2 = *reinterpret_cast<const float4*>(hc + (size_t)i2 * 256 + HH + c4);
                float4 v3 = *reinterpret_cast<const float4*>(hc + (size_t)i3 * 256 + HH + c4);
                acc.x += (v0.x + v1.x) + (v2.x + v3.x);
                acc.y += (v0.y + v1.y) + (v2.y + v3.y);
                acc.z += (v0.z + v1.z) + (v2.z + v3.z);
                acc.w += (v0.w + v1.w) + (v2.w + v3.w);
            }
            for (; p < e; p++) {
                int i0 = __ldg(&g_colidx[p]);
                float4 v0 = *reinterpret_cast<const float4*>(hc + (size_t)i0 * 256 + HH + c4);
                acc.x += v0.x; acc.y += v0.y; acc.z += v0.z; acc.w += v0.w;
            }
            float inv = 1.f / g_denom[node];
            float4 self = *reinterpret_cast<const float4*>(hc + (size_t)node * 256 + c4);
            float4 v;
            v.x = self.x + bb.x + acc.x * inv;
            v.y = self.y + bb.y + acc.y * inv;
            v.z = self.z + bb.z + acc.z * inv;
            v.w = self.w + bb.w + acc.w * inv;
            *reinterpret_cast<float4*>(hc + (size_t)node * 256 + c4) = v;
            s0 += v.x; s1 += v.y; s2 += v.z; s3 += v.w;
            q0 += v.x * v.x; q1 += v.y * v.y; q2 += v.z * v.z; q3 += v.w * v.w;
        }
        atomicAdd(&sst[c4 + 0], s0);
        atomicAdd(&sst[c4 + 1], s1);
        atomicAdd(&sst[c4 + 2], s2);
        atomicAdd(&sst[c4 + 3], s3);
        atomicAdd(&sst[HH + c4 + 0], q0);
        atomicAdd(&sst[HH + c4 + 1], q1);
        atomicAdd(&sst[HH + c4 + 2], q2);
        atomicAdd(&sst[HH + c4 + 3], q3);
    }
    __syncthreads();
    if (tid < 256) atomicAdd(&g_stats[tid], sst[tid]);
}

__global__ void k_combine(float* __restrict__ pre, const float* __restrict__ bias,
                          int M, int rows) {
    const int Hc = blockDim.x;
    int c = threadIdx.x;
    int r0 = blockIdx.x * rows;
    int r1 = min(r0 + rows, M);
    float bb = bias[c];
    float s = 0.f, s2 = 0.f;
    for (int r = r0; r < r1; r++) {
        float v = pre[(size_t)r * Hc + c] + bb;
        pre[(size_t)r * Hc + c] = v;
        s += v;
        s2 += v * v;
    }
    atomicAdd(&g_stats[c], s);
    atomicAdd(&g_stats[Hc + c], s2);
}

__global__ void k_finalize(const float* __restrict__ gamma, const float* __restrict__ beta, int M) {
    int c = threadIdx.x;
    int Hc = blockDim.x;
    float inv_m = 1.f / (float)M;
    float mean = g_stats[c] * inv_m;
    float var = g_stats[Hc + c] * inv_m - mean * mean;
    float a = gamma[c] * rsqrtf(var + EPSV);
    g_ab[c] = a;
    g_ab[Hc + c] = beta[c] - mean * a;
    g_stats[c] = 0.f;
    g_stats[Hc + c] = 0.f;
}

__global__ void k_norm(const float* __restrict__ pre, float* __restrict__ h,
                       const float* __restrict__ resid) {
    int i = blockIdx.x * blockDim.x + threadIdx.x;
    if (i >= NN * 32) return;
    int r = i >> 5, q = i & 31;
    float4 p = *reinterpret_cast<const float4*>(pre + (size_t)r * 256 + q * 4);
    float4 a = *reinterpret_cast<const float4*>(g_ab + q * 4);
    float4 b = *reinterpret_cast<const float4*>(g_ab + HH + q * 4);
    float4 v;
    v.x = fmaf(p.x, a.x, b.x); v.y = fmaf(p.y, a.y, b.y);
    v.z = fmaf(p.z, a.z, b.z); v.w = fmaf(p.w, a.w, b.w);
    if (resid) {
        float4 rr = *reinterpret_cast<const float4*>(resid + (size_t)r * HH + q * 4);
        v.x += rr.x; v.y += rr.y; v.z += rr.z; v.w += rr.w;
    }
    v.x = fmaxf(v.x, 0.f); v.y = fmaxf(v.y, 0.f);
    v.z = fmaxf(v.z, 0.f); v.w = fmaxf(v.w, 0.f);
    *reinterpret_cast<float4*>(h + (size_t)r * HH + q * 4) = v;
}

__global__ void k_output(const float* __restrict__ zpre, const float* __restrict__ W2,
                         const float* __restrict__ b2, float* __restrict__ out) {
    int gtid = blockIdx.x * blockDim.x + threadIdx.x;
    int node = gtid >> 5;
    int lane = gtid & 31;
    if (node >= NN) return;
    float acc = 0.f;
    #pragma unroll
    for (int j = lane; j < 64; j += 32) {
        float v = fmaf(zpre[(size_t)node * 64 + j], g_ab[j], g_ab[64 + j]);
        v = fmaxf(v, 0.f);
        acc += v * W2[j];
    }
    #pragma unroll
    for (int o = 16; o; o >>= 1) acc += __shfl_xor_sync(0xFFFFFFFFu, acc, o);
    if (lane == 0) out[node] = acc + b2[0];
}

// ---------------- host orchestration ------------------------------------------
extern "C" void kernel_launch(void* const* d_in, const int* in_sizes, int n_in,
                              void* d_out, int out_size) {
    const float* inputs   = (const float*)d_in[0];
    const int*   graph    = (const int*)  d_in[1];
    const float* Wself0   = (const float*)d_in[2];
    const float* Wneigh0  = (const float*)d_in[3];
    const float* b0       = (const float*)d_in[4];
    const float* Wself    = (const float*)d_in[5];
    const float* Wneigh   = (const float*)d_in[6];
    const float* bvec     = (const float*)d_in[7];
    const float* bn_gamma = (const float*)d_in[8];
    const float* bn_beta  = (const float*)d_in[9];
    const float* W1       = (const float*)d_in[10];
    const float* b1       = (const float*)d_in[11];
    const float* bng1     = (const float*)d_in[12];
    const float* bnb1     = (const float*)d_in[13];
    const float* W2       = (const float*)d_in[14];
    const float* b2       = (const float*)d_in[15];
    float* out = (float*)d_out;

    float *h, *hc, *z;
    __nv_bfloat16 *B0h, *B0l, *BLh, *BLl;
    cudaGetSymbolAddress((void**)&h,   g_h);
    cudaGetSymbolAddress((void**)&hc,  g_hc);
    cudaGetSymbolAddress((void**)&z,   g_z);
    cudaGetSymbolAddress((void**)&B0h, g_B0h);
    cudaGetSymbolAddress((void**)&B0l, g_B0l);
    cudaGetSymbolAddress((void**)&BLh, g_BLh);
    cudaGetSymbolAddress((void**)&BLl, g_BLl);

    // Unconditional + idempotent (no static guards). Executes immediately even
    // if called during capture; first (correctness) call precedes capture.
    cudaFuncSetAttribute(gemm_split, cudaFuncAttributeMaxDynamicSharedMemorySize, 2 * STAGE_B);

    const int TB = 256;
    const int gN = (NN + TB - 1) / TB;
    const int gE = (EE + TB - 1) / TB;
    const dim3 gemmGrid(2, (NN + 127) / 128);
    const int gNorm = (NN * 32 + TB - 1) / TB;
    const int gAgg = (NN + 127) / 128;

    cudaStream_t s2 = 0;
    cudaEvent_t evFork = 0, evJoin = 0;
    bool forked = (cudaStreamCreateWithFlags(&s2, cudaStreamNonBlocking) == cudaSuccess);
    if (forked) {
        cudaEventCreateWithFlags(&evFork, cudaEventDisableTiming);
        cudaEventCreateWithFlags(&evJoin, cudaEventDisableTiming);
    }
    cudaStream_t sc = forked ? s2 : 0;

    // ---- main stream: layer-0 weight conversion ----
    k_convW0<<<(256 * K0P + TB - 1) / TB, TB>>>(Wself0, Wneigh0);

    if (forked) {
        cudaEventRecord(evFork, 0);
        cudaStreamWaitEvent(s2, evFork, 0);
    }

    // ---- CSR branch (overlaps layer-0 GEMM) ----
    k_convWL<<<(3 * 256 * HH + TB - 1) / TB, TB, 0, sc>>>(Wself, Wneigh);
    k_zero_deg<<<gN, TB, 0, sc>>>();
    k_count<<<gE, TB, 0, sc>>>(graph);
    k_scan1<<<(NN + 1023) / 1024, 1024, 0, sc>>>();
    k_scan2<<<1, 32, 0, sc>>>();
    k_scan3<<<gN, TB, 0, sc>>>();
    k_fill<<<gE, TB, 0, sc>>>(graph);
    if (forked) cudaEventRecord(evJoin, s2);

    // ---- layer 0 GEMM (concurrent with CSR branch) ----
    gemm_split<<<gemmGrid, 256, 2 * STAGE_B>>>(inputs, FIN, K0P, B0h, B0l, hc, NN, 256);

    if (forked) cudaStreamWaitEvent(0, evJoin, 0);

    // ---- layer 0 epilogue ----
    k_aggcomb<<<gAgg, 256>>>(hc, b0);
    k_finalize<<<1, HH>>>(bn_gamma, bn_beta, NN);
    k_norm<<<gNorm, TB>>>(hc, h, nullptr);

    // ---- layers 1..3 ----
    for (int l = 0; l < 3; l++) {
        gemm_split<<<gemmGrid, 256, 2 * STAGE_B>>>(h, HH, HH,
                                                   BLh + (size_t)l * 256 * HH,
                                                   BLl + (size_t)l * 256 * HH,
                                                   hc, NN, 256);
        k_aggcomb<<<gAgg, 256>>>(hc, bvec + (size_t)l * HH);
        k_finalize<<<1, HH>>>(bn_gamma + (size_t)(l + 1) * HH, bn_beta + (size_t)(l + 1) * HH, NN);
        k_norm<<<gNorm, TB>>>(hc, h, h);
    }

    // ---- head ----
    sgemm<64, 4><<<dim3(1, (NN + 127) / 128), 256>>>(h, W1, z, NN, HH, 64);
    k_combine<<<(NN + 127) / 128, 64>>>(z, b1, NN, 128);
    k_finalize<<<1, 64>>>(bng1, bnb1, NN);
    k_output<<<(NN * 32 + TB - 1) / TB, TB>>>(z, W2, b2, out);

    (void)in_sizes; (void)n_in; (void)out_size;
}

// round 11
// speedup vs baseline: 1.1220x; 1.1220x over previous
#include <cuda_runtime.h>
#include <cuda_bf16.h>
#include <math.h>
#include <stdint.h>

#define NN   100000
#define EE   1600000
#define FIN  700
#define K0P  704
#define HH   128
#define EPSV 1e-5f

// ---------------- scratch (static device globals; zero-init, no runtime alloc) ----
__device__ float g_h  [(size_t)NN * HH];
__device__ float g_hc [(size_t)NN * 256];        // [self(128) | neigh(128)] per row
__device__ float g_z  [(size_t)NN * 128];        // head pre-activations (stride 128)
__device__ float g_denom[NN];
__device__ int   g_deg[NN];
__device__ int   g_rowptr[NN + 1];
__device__ int   g_colidx[EE];
__device__ int   g_bsums[128];
__device__ __align__(16) float g_stats[256];
__device__ __align__(16) float g_ab[256];

// bf16 split weights (A operands are split in-GEMM)
__device__ __nv_bfloat16 g_B0h[256 * K0P];
__device__ __nv_bfloat16 g_B0l[256 * K0P];
__device__ __nv_bfloat16 g_BLh[3 * 256 * HH];
__device__ __nv_bfloat16 g_BLl[3 * 256 * HH];
__device__ __nv_bfloat16 g_BHh[128 * HH];        // head W1 padded to 128 cols
__device__ __nv_bfloat16 g_BHl[128 * HH];

// ---------------- helpers ------------------------------------------------------
__device__ __forceinline__ void split_bf16(float x, __nv_bfloat16& h, __nv_bfloat16& l) {
    h = __float2bfloat16(x);
    l = __float2bfloat16(x - __bfloat162float(h));
}
__device__ __forceinline__ uint32_t pkbf2(__nv_bfloat16 a, __nv_bfloat16 b) {
    __nv_bfloat162 t = __halves2bfloat162(a, b);
    return *reinterpret_cast<uint32_t*>(&t);
}
__device__ __forceinline__ void cp16(uint32_t s, const void* g) {
    asm volatile("cp.async.cg.shared.global [%0], [%1], 16;" :: "r"(s), "l"(g));
}
__device__ __forceinline__ void ldsm4(uint32_t& r0, uint32_t& r1, uint32_t& r2, uint32_t& r3, uint32_t a) {
    asm volatile("ldmatrix.sync.aligned.m8n8.x4.shared.b16 {%0,%1,%2,%3}, [%4];"
                 : "=r"(r0), "=r"(r1), "=r"(r2), "=r"(r3) : "r"(a));
}
__device__ __forceinline__ void mma16816(float* c, const uint32_t* a, const uint32_t* b) {
    asm volatile("mma.sync.aligned.m16n8k16.row.col.f32.bf16.bf16.f32 "
                 "{%0,%1,%2,%3}, {%4,%5,%6,%7}, {%8,%9}, {%0,%1,%2,%3};"
                 : "+f"(c[0]), "+f"(c[1]), "+f"(c[2]), "+f"(c[3])
                 : "r"(a[0]), "r"(a[1]), "r"(a[2]), "r"(a[3]), "r"(b[0]), "r"(b[1]));
}

// ---------------- CSR construction --------------------------------------------
__global__ void k_zero_deg() {
    int i = blockIdx.x * blockDim.x + threadIdx.x;
    if (i < NN) g_deg[i] = 0;
}
__global__ void k_count(const int* __restrict__ graph) {
    int e = blockIdx.x * blockDim.x + threadIdx.x;
    if (e < EE) atomicAdd(&g_deg[graph[2 * e + 1]], 1);
}
__global__ void k_scan1() {
    __shared__ int s[1024];
    int tid = threadIdx.x;
    int i = blockIdx.x * 1024 + tid;
    int v = (i < NN) ? g_deg[i] : 0;
    s[tid] = v;
    __syncthreads();
    #pragma unroll
    for (int off = 1; off < 1024; off <<= 1) {
        int t = (tid >= off) ? s[tid - off] : 0;
        __syncthreads();
        s[tid] += t;
        __syncthreads();
    }
    if (i < NN) g_rowptr[i + 1] = s[tid];
    if (tid == 1023) g_bsums[blockIdx.x] = s[1023];
}
__global__ void k_scan2() {
    if (threadIdx.x == 0) {
        const int nb = (NN + 1023) / 1024;
        int acc = 0;
        for (int i = 0; i < nb; i++) { int t = g_bsums[i]; g_bsums[i] = acc; acc += t; }
    }
}
__global__ void k_scan3() {
    int i = blockIdx.x * blockDim.x + threadIdx.x;
    if (i >= NN) return;
    g_rowptr[i + 1] += g_bsums[i >> 10];
    if (i == 0) g_rowptr[0] = 0;
    int d = g_deg[i];
    g_denom[i] = (float)((d > 1) ? d : 1);
    g_deg[i] = 0;
}
__global__ void k_fill(const int* __restrict__ graph) {
    int e = blockIdx.x * blockDim.x + threadIdx.x;
    if (e >= EE) return;
    int src = graph[2 * e + 0];
    int dst = graph[2 * e + 1];
    int pos = g_rowptr[dst] + atomicAdd(&g_deg[dst], 1);
    g_colidx[pos] = src;
}

// ---------------- weight conversion --------------------------------------------
__global__ void k_convW0(const float* __restrict__ Ws, const float* __restrict__ Wn) {
    int idx = blockIdx.x * blockDim.x + threadIdx.x;
    if (idx >= 256 * K0P) return;
    int n = idx / K0P, k = idx % K0P;
    float v = 0.f;
    if (k < FIN) v = (n < HH) ? Ws[(size_t)k * HH + n] : Wn[(size_t)k * HH + (n - HH)];
    split_bf16(v, g_B0h[idx], g_B0l[idx]);
}
__global__ void k_convWL(const float* __restrict__ Ws, const float* __restrict__ Wn) {
    int idx = blockIdx.x * blockDim.x + threadIdx.x;
    if (idx >= 3 * 256 * HH) return;
    int l = idx / (256 * HH);
    int rem = idx % (256 * HH);
    int n = rem / HH, k = rem % HH;
    float v = (n < HH) ? Ws[(size_t)l * HH * HH + k * HH + n]
                       : Wn[(size_t)l * HH * HH + k * HH + (n - HH)];
    split_bf16(v, g_BLh[idx], g_BLl[idx]);
}
__global__ void k_convW1(const float* __restrict__ W1) {
    int idx = blockIdx.x * blockDim.x + threadIdx.x;
    if (idx >= 128 * HH) return;
    int n = idx / HH, k = idx % HH;
    float v = (n < 64) ? W1[(size_t)k * 64 + n] : 0.f;
    split_bf16(v, g_BHh[idx], g_BHl[idx]);
}

// ---------------- split-precision tensor GEMM, fp32 A fed in-kernel ------------
// (byte-exact R6 configuration: BM=128, BN=128, BK=16, 2-stage, static 48KB smem)
#define TILE_B 6144
#define STAGE_B 24576
__global__ void __launch_bounds__(256) gemm_split(
    const float* __restrict__ A, int K, int Kpad,
    const __nv_bfloat16* __restrict__ Bh0, const __nv_bfloat16* __restrict__ Bl0,
    float* __restrict__ C, int M, int NCs)
{
    __shared__ __align__(16) char smem[49152];
    const uint32_t sb = (uint32_t)__cvta_generic_to_shared(smem);
    const int tid = threadIdx.x;
    const int bx = blockIdx.x, by = blockIdx.y;
    const int row0 = by * 128;
    const __nv_bfloat16* Bh = Bh0 + (size_t)bx * 128 * Kpad;
    const __nv_bfloat16* Bl = Bl0 + (size_t)bx * 128 * Kpad;
    const int KT = Kpad >> 4;

    const int ar = tid >> 1, aq = tid & 1;
    const int agr = row0 + ar;
    const float* Arow = A + (size_t)agr * K;

    float4 hv0, hv1;
    float4 nv0, nv1;

    auto ldgA = [&](int kt, float4& v0, float4& v1) {
        v0 = make_float4(0.f, 0.f, 0.f, 0.f);
        v1 = v0;
        int kb = kt * 16 + aq * 8;
        if (agr < M) {
            if (kb + 3 < K) v0 = *reinterpret_cast<const float4*>(Arow + kb);
            if (kb + 7 < K) v1 = *reinterpret_cast<const float4*>(Arow + kb + 4);
        }
    };
    auto stsA = [&](int stage, float4 v0, float4 v1) {
        float f[8] = {v0.x, v0.y, v0.z, v0.w, v1.x, v1.y, v1.z, v1.w};
        __nv_bfloat16 hh[8], ll[8];
        #pragma unroll
        for (int i = 0; i < 8; i++) split_bf16(f[i], hh[i], ll[i]);
        uint4 hvv, lvv;
        hvv.x = pkbf2(hh[0], hh[1]); hvv.y = pkbf2(hh[2], hh[3]);
        hvv.z = pkbf2(hh[4], hh[5]); hvv.w = pkbf2(hh[6], hh[7]);
        lvv.x = pkbf2(ll[0], ll[1]); lvv.y = pkbf2(ll[2], ll[3]);
        lvv.z = pkbf2(ll[4], ll[5]); lvv.w = pkbf2(ll[6], ll[7]);
        char* dst = smem + stage * STAGE_B + ar * 48 + aq * 16;
        *reinterpret_cast<uint4*>(dst) = hvv;
        *reinterpret_cast<uint4*>(dst + TILE_B) = lvv;
    };
    auto cpB = [&](int kt) {
        uint32_t base = sb + (uint32_t)(kt & 1) * STAGE_B + 2u * TILE_B;
        int r = tid >> 1, q = tid & 1;
        uint32_t so = base + (uint32_t)(r * 48 + q * 16);
        size_t gb = (size_t)r * Kpad + kt * 16 + q * 8;
        cp16(so, Bh + gb);
        cp16(so + TILE_B, Bl + gb);
        asm volatile("cp.async.commit_group;");
    };

    {
        float4 a0, a1;
        ldgA(0, a0, a1);
        ldgA(1, hv0, hv1);
        cpB(0);
        cpB(1);
        stsA(0, a0, a1);
    }

    const int lane = tid & 31, w = tid >> 5;
    const int wm = w >> 2, wn = w & 3;
    const int lr = lane >> 2, lc = lane & 3;
    const int mat = lane >> 3, r8 = lane & 7;

    float acc[4][4][4];
    #pragma unroll
    for (int a = 0; a < 4; a++)
        #pragma unroll
        for (int b = 0; b < 4; b++)
            #pragma unroll
            for (int d = 0; d < 4; d++) acc[a][b][d] = 0.f;

    for (int kt = 0; kt < KT; ++kt) {
        if (kt < KT - 1) asm volatile("cp.async.wait_group 1;");
        else             asm volatile("cp.async.wait_group 0;");
        __syncthreads();

        if (kt + 1 < KT) stsA((kt + 1) & 1, hv0, hv1);
        if (kt + 2 < KT) ldgA(kt + 2, nv0, nv1);

        uint32_t base = sb + (uint32_t)(kt & 1) * STAGE_B;

        uint32_t bh[2][4], bl[2][4];
        #pragma unroll
        for (int p = 0; p < 2; p++) {
            int brow = wn * 32 + p * 16 + r8 + (mat >> 1) * 8;
            uint32_t addr = base + 2u * TILE_B + (uint32_t)(brow * 48 + ((mat & 1) * 8) * 2);
            ldsm4(bh[p][0], bh[p][1], bh[p][2], bh[p][3], addr);
            ldsm4(bl[p][0], bl[p][1], bl[p][2], bl[p][3], addr + TILE_B);
        }
        #pragma unroll
        for (int mf = 0; mf < 4; ++mf) {
            int arow = wm * 64 + mf * 16 + r8 + (mat & 1) * 8;
            uint32_t aaddr = base + (uint32_t)(arow * 48 + ((mat >> 1) * 8) * 2);
            uint32_t ahr[4], alr[4];
            ldsm4(ahr[0], ahr[1], ahr[2], ahr[3], aaddr);
            ldsm4(alr[0], alr[1], alr[2], alr[3], aaddr + TILE_B);
            #pragma unroll
            for (int nf = 0; nf < 4; ++nf) {
                const uint32_t* bhp = &bh[nf >> 1][(nf & 1) * 2];
                const uint32_t* blp = &bl[nf >> 1][(nf & 1) * 2];
                mma16816(acc[mf][nf], ahr, bhp);
                mma16816(acc[mf][nf], alr, bhp);
                mma16816(acc[mf][nf], ahr, blp);
            }
        }
        __syncthreads();
        if (kt + 2 < KT) {
            cpB(kt + 2);
            hv0 = nv0; hv1 = nv1;
        }
    }

    #pragma unroll
    for (int mf = 0; mf < 4; ++mf) {
        #pragma unroll
        for (int nf = 0; nf < 4; ++nf) {
            int r = row0 + wm * 64 + mf * 16 + lr;
            int cc = bx * 128 + wn * 32 + nf * 8 + lc * 2;
            if (r < M)
                *reinterpret_cast<float2*>(C + (size_t)r * NCs + cc) =
                    make_float2(acc[mf][nf][0], acc[mf][nf][1]);
            if (r + 8 < M)
                *reinterpret_cast<float2*>(C + (size_t)(r + 8) * NCs + cc) =
                    make_float2(acc[mf][nf][2], acc[mf][nf][3]);
        }
    }
}

// ---------------- fused CSR gather + bias + BN stats (warp-per-node) -----------
#define AGG_NPW 16
__global__ void __launch_bounds__(256) k_aggcomb(float* __restrict__ hc,
                                                 const float* __restrict__ bias) {
    __shared__ float sst[256];
    const int tid = threadIdx.x;
    const int lane = tid & 31;
    const int gw = blockIdx.x * 8 + (tid >> 5);
    const int c4 = lane * 4;
    const int n0 = gw * AGG_NPW;
    if (tid < 256) sst[tid] = 0.f;
    __syncthreads();

    if (n0 < NN) {
        const int n1 = min(n0 + AGG_NPW, NN);
        float4 bb = *reinterpret_cast<const float4*>(bias + c4);
        float s0 = 0.f, s1 = 0.f, s2 = 0.f, s3 = 0.f;
        float q0 = 0.f, q1 = 0.f, q2 = 0.f, q3 = 0.f;

        for (int node = n0; node < n1; node++) {
            int p = g_rowptr[node];
            const int e = g_rowptr[node + 1];
            float4 acc = make_float4(0.f, 0.f, 0.f, 0.f);
            for (; p + 3 < e; p += 4) {
                int i0 = __ldg(&g_colidx[p]);
                int i1 = __ldg(&g_colidx[p + 1]);
                int i2 = __ldg(&g_colidx[p + 2]);
                int i3 = __ldg(&g_colidx[p + 3]);
                float4 v0 = *reinterpret_cast<const float4*>(hc + (size_t)i0 * 256 + HH + c4);
                float4 v1 = *reinterpret_cast<const float4*>(hc + (size_t)i1 * 256 + HH + c4);
                float4 v2 = *reinterpret_cast<const float4*>(hc + (size_t)i2 * 256 + HH + c4);
                float4 v3 = *reinterpret_cast<const float4*>(hc + (size_t)i3 * 256 + HH + c4);
                acc.x += (v0.x + v1.x) + (v2.x + v3.x);
                acc.y += (v0.y + v1.y) + (v2.y + v3.y);
                acc.z += (v0.z + v1.z) + (v2.z + v3.z);
                acc.w += (v0.w + v1.w) + (v2.w + v3.w);
            }
            for (; p < e; p++) {
                int i0 = __ldg(&g_colidx[p]);
                float4 v0 = *reinterpret_cast<const float4*>(hc + (size_t)i0 * 256 + HH + c4);
                acc.x += v0.x; acc.y += v0.y; acc.z += v0.z; acc.w += v0.w;
            }
            float inv = 1.f / g_denom[node];
            float4 self = *reinterpret_cast<const float4*>(hc + (size_t)node * 256 + c4);
            float4 v;
            v.x = self.x + bb.x + acc.x * inv;
            v.y = self.y + bb.y + acc.y * inv;
            v.z = self.z + bb.z + acc.z * inv;
            v.w = self.w + bb.w + acc.w * inv;
            *reinterpret_cast<float4*>(hc + (size_t)node * 256 + c4) = v;
            s0 += v.x; s1 += v.y; s2 += v.z; s3 += v.w;
            q0 += v.x * v.x; q1 += v.y * v.y; q2 += v.z * v.z; q3 += v.w * v.w;
        }
        atomicAdd(&sst[c4 + 0], s0);
        atomicAdd(&sst[c4 + 1], s1);
        atomicAdd(&sst[c4 + 2], s2);
        atomicAdd(&sst[c4 + 3], s3);
        atomicAdd(&sst[HH + c4 + 0], q0);
        atomicAdd(&sst[HH + c4 + 1], q1);
        atomicAdd(&sst[HH + c4 + 2], q2);
        atomicAdd(&sst[HH + c4 + 3], q3);
    }
    __syncthreads();
    if (tid < 256) atomicAdd(&g_stats[tid], sst[tid]);
}

// head: pre stride 128, active cols = 64 (blockDim.x)
__global__ void k_combineH(float* __restrict__ pre, const float* __restrict__ bias,
                           int rows) {
    int c = threadIdx.x;                 // 64 threads
    int r0 = blockIdx.x * rows;
    int r1 = min(r0 + rows, NN);
    float bb = bias[c];
    float s = 0.f, s2 = 0.f;
    for (int r = r0; r < r1; r++) {
        float v = pre[(size_t)r * 128 + c] + bb;
        pre[(size_t)r * 128 + c] = v;
        s += v;
        s2 += v * v;
    }
    atomicAdd(&g_stats[c], s);
    atomicAdd(&g_stats[64 + c], s2);
}

// compute BN scale/offset, then self-zero stats for the next accumulation
__global__ void k_finalize(const float* __restrict__ gamma, const float* __restrict__ beta, int M) {
    int c = threadIdx.x;
    int Hc = blockDim.x;
    float inv_m = 1.f / (float)M;
    float mean = g_stats[c] * inv_m;
    float var = g_stats[Hc + c] * inv_m - mean * mean;
    float a = gamma[c] * rsqrtf(var + EPSV);
    g_ab[c] = a;
    g_ab[Hc + c] = beta[c] - mean * a;
    g_stats[c] = 0.f;
    g_stats[Hc + c] = 0.f;
}

// BN + (residual) + ReLU -> h
__global__ void k_norm(const float* __restrict__ pre, float* __restrict__ h,
                       const float* __restrict__ resid) {
    int i = blockIdx.x * blockDim.x + threadIdx.x;
    if (i >= NN * 32) return;
    int r = i >> 5, q = i & 31;
    float4 p = *reinterpret_cast<const float4*>(pre + (size_t)r * 256 + q * 4);
    float4 a = *reinterpret_cast<const float4*>(g_ab + q * 4);
    float4 b = *reinterpret_cast<const float4*>(g_ab + HH + q * 4);
    float4 v;
    v.x = fmaf(p.x, a.x, b.x); v.y = fmaf(p.y, a.y, b.y);
    v.z = fmaf(p.z, a.z, b.z); v.w = fmaf(p.w, a.w, b.w);
    if (resid) {
        float4 rr = *reinterpret_cast<const float4*>(resid + (size_t)r * HH + q * 4);
        v.x += rr.x; v.y += rr.y; v.z += rr.z; v.w += rr.w;
    }
    v.x = fmaxf(v.x, 0.f); v.y = fmaxf(v.y, 0.f);
    v.z = fmaxf(v.z, 0.f); v.w = fmaxf(v.w, 0.f);
    *reinterpret_cast<float4*>(h + (size_t)r * HH + q * 4) = v;
}

// final head: BN -> relu -> @W2 + b2, one warp per node (zpre stride 128)
__global__ void k_output(const float* __restrict__ zpre, const float* __restrict__ W2,
                         const float* __restrict__ b2, float* __restrict__ out) {
    int gtid = blockIdx.x * blockDim.x + threadIdx.x;
    int node = gtid >> 5;
    int lane = gtid & 31;
    if (node >= NN) return;
    float acc = 0.f;
    #pragma unroll
    for (int j = lane; j < 64; j += 32) {
        float v = fmaf(zpre[(size_t)node * 128 + j], g_ab[j], g_ab[64 + j]);
        v = fmaxf(v, 0.f);
        acc += v * W2[j];
    }
    #pragma unroll
    for (int o = 16; o; o >>= 1) acc += __shfl_xor_sync(0xFFFFFFFFu, acc, o);
    if (lane == 0) out[node] = acc + b2[0];
}

// ---------------- host orchestration ------------------------------------------
extern "C" void kernel_launch(void* const* d_in, const int* in_sizes, int n_in,
                              void* d_out, int out_size) {
    const float* inputs   = (const float*)d_in[0];
    const int*   graph    = (const int*)  d_in[1];
    const float* Wself0   = (const float*)d_in[2];
    const float* Wneigh0  = (const float*)d_in[3];
    const float* b0       = (const float*)d_in[4];
    const float* Wself    = (const float*)d_in[5];
    const float* Wneigh   = (const float*)d_in[6];
    const float* bvec     = (const float*)d_in[7];
    const float* bn_gamma = (const float*)d_in[8];
    const float* bn_beta  = (const float*)d_in[9];
    const float* W1       = (const float*)d_in[10];
    const float* b1       = (const float*)d_in[11];
    const float* bng1     = (const float*)d_in[12];
    const float* bnb1     = (const float*)d_in[13];
    const float* W2       = (const float*)d_in[14];
    const float* b2       = (const float*)d_in[15];
    float* out = (float*)d_out;

    float *h, *hc, *z;
    __nv_bfloat16 *B0h, *B0l, *BLh, *BLl, *BHh, *BHl;
    cudaGetSymbolAddress((void**)&h,   g_h);
    cudaGetSymbolAddress((void**)&hc,  g_hc);
    cudaGetSymbolAddress((void**)&z,   g_z);
    cudaGetSymbolAddress((void**)&B0h, g_B0h);
    cudaGetSymbolAddress((void**)&B0l, g_B0l);
    cudaGetSymbolAddress((void**)&BLh, g_BLh);
    cudaGetSymbolAddress((void**)&BLl, g_BLl);
    cudaGetSymbolAddress((void**)&BHh, g_BHh);
    cudaGetSymbolAddress((void**)&BHl, g_BHl);

    const int TB = 256;
    const int gN = (NN + TB - 1) / TB;
    const int gE = (EE + TB - 1) / TB;
    const dim3 gemmGrid(2, (NN + 127) / 128);
    const dim3 headGrid(1, (NN + 127) / 128);
    const int gNorm = (NN * 32 + TB - 1) / TB;
    const int gAgg = (NN + 127) / 128;

    cudaStream_t s2 = 0;
    cudaEvent_t evFork = 0, evJoin = 0;
    bool forked = (cudaStreamCreateWithFlags(&s2, cudaStreamNonBlocking) == cudaSuccess);
    if (forked) {
        cudaEventCreateWithFlags(&evFork, cudaEventDisableTiming);
        cudaEventCreateWithFlags(&evJoin, cudaEventDisableTiming);
    }
    cudaStream_t sc = forked ? s2 : 0;

    // ---- main stream: layer-0 weight conversion ----
    k_convW0<<<(256 * K0P + TB - 1) / TB, TB>>>(Wself0, Wneigh0);

    if (forked) {
        cudaEventRecord(evFork, 0);
        cudaStreamWaitEvent(s2, evFork, 0);
    }

    // ---- CSR branch (overlaps layer-0 GEMM) ----
    k_convWL<<<(3 * 256 * HH + TB - 1) / TB, TB, 0, sc>>>(Wself, Wneigh);
    k_convW1<<<(128 * HH + TB - 1) / TB, TB, 0, sc>>>(W1);
    k_zero_deg<<<gN, TB, 0, sc>>>();
    k_count<<<gE, TB, 0, sc>>>(graph);
    k_scan1<<<(NN + 1023) / 1024, 1024, 0, sc>>>();
    k_scan2<<<1, 32, 0, sc>>>();
    k_scan3<<<gN, TB, 0, sc>>>();
    k_fill<<<gE, TB, 0, sc>>>(graph);
    if (forked) cudaEventRecord(evJoin, s2);

    // ---- layer 0 GEMM (concurrent with CSR branch) ----
    gemm_split<<<gemmGrid, 256>>>(inputs, FIN, K0P, B0h, B0l, hc, NN, 256);

    if (forked) cudaStreamWaitEvent(0, evJoin, 0);

    // ---- layer 0 epilogue ----
    k_aggcomb<<<gAgg, 256>>>(hc, b0);
    k_finalize<<<1, HH>>>(bn_gamma, bn_beta, NN);
    k_norm<<<gNorm, TB>>>(hc, h, nullptr);

    // ---- layers 1..3 ----
    for (int l = 0; l < 3; l++) {
        gemm_split<<<gemmGrid, 256>>>(h, HH, HH,
                                      BLh + (size_t)l * 256 * HH,
                                      BLl + (size_t)l * 256 * HH,
                                      hc, NN, 256);
        k_aggcomb<<<gAgg, 256>>>(hc, bvec + (size_t)l * HH);
        k_finalize<<<1, HH>>>(bn_gamma + (size_t)(l + 1) * HH, bn_beta + (size_t)(l + 1) * HH, NN);
        k_norm<<<gNorm, TB>>>(hc, h, h);
    }

    // ---- head (tensor GEMM on padded W1, z stride 128) ----
    gemm_split<<<headGrid, 256>>>(h, HH, HH, BHh, BHl, z, NN, 128);
    k_combineH<<<(NN + 127) / 128, 64>>>(z, b1, 128);
    k_finalize<<<1, 64>>>(bng1, bnb1, NN);
    k_output<<<(NN * 32 + TB - 1) / TB, TB>>>(z, W2, b2, out);

    (void)in_sizes; (void)n_in; (void)out_size;
}